// round 11
// baseline (speedup 1.0000x reference)
#include <cuda_runtime.h>
#include <cuda_bf16.h>
#include <cstdint>

// Fused autoencoder fwd + Jacobians via warp-level mma.sync (bf16 split, f32 acc).
// R11: uniform weights in __constant__, rb-sequential MMA/epilogue (reg cut),
// reduce-scatter shuffle reduction (24 vs 48 SHFL/phase), 4 CTAs/SM.
// Outputs: theta[N,2] | J_h[N,2,2] | q_hat[N,2] | J_h_dec[N,2,2] | J_h_ana[N,2,2]

#define STG_STRIDE 144
#define SM_STG   0                        // 4 warps * 32 rows * 144 = 18432
#define SM_ZB    (4 * 32 * STG_STRIDE)    // 4 matrices * 16 rows * 48 = 3072
#define SM_ABB   (SM_ZB + 4 * 16 * 48)    // 4 matrices * 16 rows * 80 = 5120
#define SM_EW    (SM_ABB + 4 * 16 * 80)   // 2 * 50 floats (lane-indexed epilogue w)
#define SM_TOT   (SM_EW + 400)

__constant__ float CWf[96];               // [E*48]: w1 interleaved(32), b1(16)
__device__   float g_scr[96];

__device__ __forceinline__ uint32_t s2u(const void* p) {
    uint32_t a;
    asm("{.reg .u64 t; cvta.to.shared.u64 t,%1; cvt.u32.u64 %0,t;}" : "=r"(a) : "l"(p));
    return a;
}
__device__ __forceinline__ void ldsm4(uint32_t& r0, uint32_t& r1, uint32_t& r2, uint32_t& r3, uint32_t a) {
    asm volatile("ldmatrix.sync.aligned.m8n8.x4.shared.b16 {%0,%1,%2,%3},[%4];"
                 : "=r"(r0), "=r"(r1), "=r"(r2), "=r"(r3) : "r"(a));
}
__device__ __forceinline__ void ldsm4t(uint32_t& r0, uint32_t& r1, uint32_t& r2, uint32_t& r3, uint32_t a) {
    asm volatile("ldmatrix.sync.aligned.m8n8.x4.trans.shared.b16 {%0,%1,%2,%3},[%4];"
                 : "=r"(r0), "=r"(r1), "=r"(r2), "=r"(r3) : "r"(a));
}
__device__ __forceinline__ void mma16816(float* d, const uint32_t* a, uint32_t b0, uint32_t b1) {
    asm volatile("mma.sync.aligned.m16n8k16.row.col.f32.bf16.bf16.f32 "
                 "{%0,%1,%2,%3},{%4,%5,%6,%7},{%8,%9},{%0,%1,%2,%3};"
                 : "+f"(d[0]), "+f"(d[1]), "+f"(d[2]), "+f"(d[3])
                 : "r"(a[0]), "r"(a[1]), "r"(a[2]), "r"(a[3]), "r"(b0), "r"(b1));
}

__device__ __forceinline__ void act(float z, float& h, float& s) {
    const float L2E = 1.442695041f, LN2 = 0.6931471806f;
    float t, g;
    asm("ex2.approx.ftz.f32 %0,%1;" : "=f"(t) : "f"(fabsf(z) * -L2E));
    asm("lg2.approx.ftz.f32 %0,%1;" : "=f"(g) : "f"(1.0f + t));
    h = fmaf(g, LN2, fmaxf(z, 0.0f));
    asm("ex2.approx.ftz.f32 %0,%1;" : "=f"(s) : "f"(fmaf(fminf(z, 0.0f), L2E, -g)));
}
__device__ __forceinline__ float trhi(float v) { return __uint_as_float(__float_as_uint(v) & 0xffff0000u); }
__device__ __forceinline__ uint32_t bfp(float a, float b) {  // a -> low half
    uint32_t r;
    asm("cvt.rn.bf16x2.f32 %0,%1,%2;" : "=r"(r) : "f"(b), "f"(a));
    return r;
}

struct Ctx {
    char*    rowPtr;
    uint32_t aBase;
    uint32_t zBase;
    uint32_t abBase;
    const float* ewf;   // smem: per E 50 floats [b2(16)|w30(16)|w31(16)|b3(2)]
    int m;
};

__device__ void phase(const Ctx& c, int E, float x0, float x1, float res[6]) {
    const float* o  = CWf + E * 48;     // uniform -> LDCU
    const float* ew = c.ewf + E * 50;   // lane-indexed -> LDS

    // layer 1 (scalar, own row)
    float hv[16], sv[16];
#pragma unroll
    for (int i = 0; i < 16; ++i) {
        float z = fmaf(o[2 * i], x0, fmaf(o[2 * i + 1], x1, o[32 + i]));
        act(z, hv[i], sv[i]);
    }
    // split hi/lo, pack bf16x2
    uint32_t ph[8], pl[8], qh[8], ql[8];
#pragma unroll
    for (int k = 0; k < 8; ++k) {
        float a = hv[2 * k], b = hv[2 * k + 1];
        float ah = trhi(a), bh = trhi(b);
        ph[k] = bfp(ah, bh);  pl[k] = bfp(a - ah, b - bh);
        a = sv[2 * k]; b = sv[2 * k + 1];
        ah = trhi(a); bh = trhi(b);
        qh[k] = bfp(ah, bh);  ql[k] = bfp(a - ah, b - bh);
    }
    __syncwarp();
    uint4* rw = (uint4*)c.rowPtr;   // row: [Hhi32|Hlo32|Shi32|Slo32|pad16]
    rw[0] = make_uint4(ph[0], ph[1], ph[2], ph[3]);
    rw[1] = make_uint4(ph[4], ph[5], ph[6], ph[7]);
    rw[2] = make_uint4(pl[0], pl[1], pl[2], pl[3]);
    rw[3] = make_uint4(pl[4], pl[5], pl[6], pl[7]);
    rw[4] = make_uint4(qh[0], qh[1], qh[2], qh[3]);
    rw[5] = make_uint4(qh[4], qh[5], qh[6], qh[7]);
    rw[6] = make_uint4(ql[0], ql[1], ql[2], ql[3]);
    rw[7] = make_uint4(ql[4], ql[5], ql[6], ql[7]);
    __syncwarp();

    // B fragments (tile-invariant within phase; used by both rb halves)
    uint32_t zh[4], zl[4], abh[8], abl[8];
    uint32_t za = c.zBase + E * 1536;
    ldsm4t(zh[0], zh[1], zh[2], zh[3], za);
    ldsm4t(zl[0], zl[1], zl[2], zl[3], za + 768);
    uint32_t aa = c.abBase + E * 2560;
    ldsm4t(abh[0], abh[1], abh[2], abh[3], aa);
    ldsm4t(abh[4], abh[5], abh[6], abh[7], aa + 32);
    ldsm4t(abl[0], abl[1], abl[2], abl[3], aa + 1280);
    ldsm4t(abl[4], abl[5], abl[6], abl[7], aa + 1280 + 32);

    // lane-indexed epilogue weights, j = m + 4*jj
    float b2v[4], w0v[4], w1v[4];
#pragma unroll
    for (int jj = 0; jj < 4; ++jj) {
        int j = c.m + 4 * jj;
        b2v[jj] = ew[j];
        w0v[jj] = ew[16 + j];
        w1v[jj] = ew[32 + j];
    }

#pragma unroll
    for (int rb = 0; rb < 2; ++rb) {
        // A fragments for this 16-row half
        uint32_t Hh[4], Hl[4], Sh[4], Sl[4];
        uint32_t ba = c.aBase + rb * (16 * STG_STRIDE);
        ldsm4(Hh[0], Hh[1], Hh[2], Hh[3], ba + 0);
        ldsm4(Hl[0], Hl[1], Hl[2], Hl[3], ba + 32);
        ldsm4(Sh[0], Sh[1], Sh[2], Sh[3], ba + 64);
        ldsm4(Sl[0], Sl[1], Sl[2], Sl[3], ba + 96);

        float Zc[2][4] = {};
        float Ac[4][4] = {};
        mma16816(Zc[0], Hh, zh[0], zh[1]);
        mma16816(Zc[1], Hh, zh[2], zh[3]);
        mma16816(Zc[0], Hh, zl[0], zl[1]);
        mma16816(Zc[1], Hh, zl[2], zl[3]);
        mma16816(Zc[0], Hl, zh[0], zh[1]);
        mma16816(Zc[1], Hl, zh[2], zh[3]);
#pragma unroll
        for (int cb = 0; cb < 4; ++cb) {
            mma16816(Ac[cb], Sh, abh[2 * cb], abh[2 * cb + 1]);
            mma16816(Ac[cb], Sh, abl[2 * cb], abl[2 * cb + 1]);
            mma16816(Ac[cb], Sl, abh[2 * cb], abh[2 * cb + 1]);
        }

        // partials for the 2 row-slots (u=0,1) of this half
        float p[2][6];
#pragma unroll
        for (int u = 0; u < 2; ++u) {
            float y0 = 0.f, y1 = 0.f, j00 = 0.f, j01 = 0.f, j10 = 0.f, j11 = 0.f;
#pragma unroll
            for (int jj = 0; jj < 4; ++jj) {
                float z = Zc[jj & 1][2 * u + (jj >> 1)] + b2v[jj];
                float h2, s2;
                act(z, h2, s2);
                float sa = s2 * Ac[jj][2 * u];
                float sb = s2 * Ac[jj][2 * u + 1];
                y0 = fmaf(w0v[jj], h2, y0);   y1 = fmaf(w1v[jj], h2, y1);
                j00 = fmaf(w0v[jj], sa, j00); j01 = fmaf(w0v[jj], sb, j01);
                j10 = fmaf(w1v[jj], sa, j10); j11 = fmaf(w1v[jj], sb, j11);
            }
            p[u][0] = y0; p[u][1] = y1; p[u][2] = j00;
            p[u][3] = j01; p[u][4] = j10; p[u][5] = j11;
        }

        // reduce-scatter across the quad: lane keeps slot u = m&1 iff m>>1 == rb
        const int u = c.m & 1;
        const bool keep = (c.m >> 1) == rb;
#pragma unroll
        for (int a = 0; a < 6; ++a) {
            float send1 = p[u ^ 1][a];
            float recv1 = __shfl_xor_sync(~0u, send1, 1);
            float cmb   = p[u][a] + recv1;
            float recv2 = __shfl_xor_sync(~0u, cmb, 2);
            float tot   = cmb + recv2;
            if (keep) res[a] = (a < 2) ? (tot + ew[48 + a]) : tot;
        }
    }
}

__global__ void __launch_bounds__(128, 4) ae_mma_kernel(
    const float* __restrict__ q,
    const float* __restrict__ ew1, const float* __restrict__ eb1,
    const float* __restrict__ ew2, const float* __restrict__ eb2,
    const float* __restrict__ ew3, const float* __restrict__ eb3,
    const float* __restrict__ dw1, const float* __restrict__ db1,
    const float* __restrict__ dw2, const float* __restrict__ db2,
    const float* __restrict__ dw3, const float* __restrict__ db3,
    float* __restrict__ out, int N)
{
    __shared__ __align__(16) char sm[SM_TOT];
    const int t = threadIdx.x;
    const float* W1g[2] = {ew1, dw1};
    const float* W2g[2] = {ew2, dw2};

    // Bz: col permutation jmap(col)=((col&7)>>1)+((col>>3)<<2)+((col&1)<<3)
    for (int idx = t; idx < 512; idx += 128) {
        int E = idx >> 8, r = idx & 255, k = r >> 4, col = r & 15;
        int j = ((col & 7) >> 1) + ((col >> 3) << 2) + ((col & 1) << 3);
        float wv = W2g[E][j * 16 + k];
        float hi = trhi(wv), lo = wv - hi;
        char* bz = sm + SM_ZB + E * 1536;
        *(__nv_bfloat16*)(bz + k * 48 + col * 2)       = __float2bfloat16(hi);
        *(__nv_bfloat16*)(bz + 768 + k * 48 + col * 2) = __float2bfloat16(lo);
    }
    // Babs: col=2j -> W2[j][k]*W1[k][0], col=2j+1 -> *W1[k][1]
    for (int idx = t; idx < 1024; idx += 128) {
        int E = idx >> 9, r = idx & 511, k = r >> 5, col = r & 31;
        int j = col >> 1, v = col & 1;
        float wv = W2g[E][j * 16 + k] * W1g[E][2 * k + v];
        float hi = trhi(wv), lo = wv - hi;
        char* bb = sm + SM_ABB + E * 2560;
        *(__nv_bfloat16*)(bb + k * 80 + col * 2)        = __float2bfloat16(hi);
        *(__nv_bfloat16*)(bb + 1280 + k * 80 + col * 2) = __float2bfloat16(lo);
    }
    {
        const float* B2g[2] = {eb2, db2};
        const float* W3g[2] = {ew3, dw3};
        const float* B3g[2] = {eb3, db3};
        float* ewf = (float*)(sm + SM_EW);
        if (t < 32) {
            int E = t >> 4, j = t & 15;
            float* o = ewf + E * 50;
            o[j]      = B2g[E][j];
            o[16 + j] = W3g[E][j];
            o[32 + j] = W3g[E][16 + j];
            if (j < 2) o[48 + j] = B3g[E][j];
        }
    }
    __syncthreads();

    const int l = t & 31, w = t >> 5;
    const int m = l & 3, g = l >> 2;
    const int own = 8 * m + g;
    const int ti = l >> 3, ri = l & 7;
    char* stgW = sm + SM_STG + w * 32 * STG_STRIDE;

    Ctx c;
    c.rowPtr = stgW + own * STG_STRIDE;
    c.aBase  = s2u(stgW) + (8 * (ti & 1) + ri) * STG_STRIDE + (ti >> 1) * 16;
    c.zBase  = s2u(sm + SM_ZB)  + (8 * (ti & 1) + ri) * 48 + (ti >> 1) * 16;
    c.abBase = s2u(sm + SM_ABB) + (8 * (ti & 1) + ri) * 80 + (ti >> 1) * 16;
    c.ewf = (const float*)(sm + SM_EW);
    c.m = m;

    const size_t Ns = (size_t)N;
#pragma unroll
    for (int tile = 0; tile < 2; ++tile) {
        const int n = blockIdx.x * 256 + w * 64 + tile * 32 + own;
        float2 qv = make_float2(0.f, 0.f);
        if (n < N) qv = reinterpret_cast<const float2*>(q)[n];

        float enc[6], dec[6];
        phase(c, 0, qv.x, qv.y, enc);
        phase(c, 1, enc[0], enc[1], dec);

        if (n < N) {
            float q0 = qv.x, q1 = qv.y;
            float r2  = fmaf(q0, q0, q1 * q1);
            float inv = __fdividef(1.0f, r2);
            float isr = rsqrtf(r2 + 1e-8f);
            reinterpret_cast<float2*>(out)[n]           = make_float2(enc[0], enc[1]);
            reinterpret_cast<float4*>(out + 2 * Ns)[n]  = make_float4(enc[2], enc[3], enc[4], enc[5]);
            reinterpret_cast<float2*>(out + 6 * Ns)[n]  = make_float2(dec[0], dec[1]);
            reinterpret_cast<float4*>(out + 8 * Ns)[n]  = make_float4(dec[2], dec[3], dec[4], dec[5]);
            reinterpret_cast<float4*>(out + 12 * Ns)[n] = make_float4(-q1 * inv, q0 * inv, q0 * isr, q1 * isr);
        }
    }
}

__global__ void prep_kernel(
    const float* __restrict__ ew1, const float* __restrict__ eb1,
    const float* __restrict__ dw1, const float* __restrict__ db1)
{
    const int t = threadIdx.x;
    const float* W1[2] = {ew1, dw1};
    const float* B1[2] = {eb1, db1};
    if (t < 32) {
        int E = t >> 4, i = t & 15;
        g_scr[E * 48 + 2 * i]     = W1[E][2 * i];
        g_scr[E * 48 + 2 * i + 1] = W1[E][2 * i + 1];
        g_scr[E * 48 + 32 + i]    = B1[E][i];
    }
}

extern "C" void kernel_launch(void* const* d_in, const int* in_sizes, int n_in,
                              void* d_out, int out_size) {
    prep_kernel<<<1, 32>>>((const float*)d_in[1], (const float*)d_in[2],
                           (const float*)d_in[7], (const float*)d_in[8]);
    void* cw = nullptr; void* sc = nullptr;
    cudaGetSymbolAddress(&cw, CWf);
    cudaGetSymbolAddress(&sc, g_scr);
    cudaMemcpyAsync(cw, sc, 96 * sizeof(float), cudaMemcpyDeviceToDevice, 0);

    const int N = in_sizes[0] / 2;
    const int blocks = (N + 255) / 256;
    ae_mma_kernel<<<blocks, 128>>>(
        (const float*)d_in[0],
        (const float*)d_in[1], (const float*)d_in[2],
        (const float*)d_in[3], (const float*)d_in[4],
        (const float*)d_in[5], (const float*)d_in[6],
        (const float*)d_in[7], (const float*)d_in[8],
        (const float*)d_in[9], (const float*)d_in[10],
        (const float*)d_in[11], (const float*)d_in[12],
        (float*)d_out, N);
}